// round 13
// baseline (speedup 1.0000x reference)
#include <cuda_runtime.h>

// MedianPool2d 3x3, stride 1, reflect pad (1,1,1,1)
// float32 [16, 3, 512, 512] -> same shape.
//
// R13: dual-plane interleaved tiles. Each thread computes its 4(W)x2(H) tile
// in plane p AND plane p+24 (fully independent data). All 8 LDG.128 issue at
// warp start; tile-2's load latency is hidden behind tile-1's compute. This
// attacks the correlated warp-start load stall (issue stuck at ~65% across
// R3-R12) without dependent-chain pipelining (which failed in R8/R9).
// Math body = champion R11: packed f32x2 compare-exchange on the FMA pipe for
// the vertical stage, scalar FMNMX sliding-window combine on the ALU pipe,
// SHFL halos with merged lane-0/31 fixup, 32-bit offsets.

#define W 512
#define H 512
#define PLANE2 (24u * H * W)   // offset to the paired plane

typedef unsigned long long u64;
typedef unsigned int u32;

__device__ __forceinline__ u64 pk(float x, float y) {
    u64 r; asm("mov.b64 %0, {%1, %2};" : "=l"(r) : "f"(x), "f"(y)); return r;
}
__device__ __forceinline__ float2 upk(u64 v) {
    float2 f; asm("mov.b64 {%0, %1}, %2;" : "=f"(f.x), "=f"(f.y) : "l"(v)); return f;
}

// packed compare-exchange on 2 fp32 lanes: lo=min, hi=max (FMA pipe)
__device__ __forceinline__ void cex2(u64 a, u64 b, u64& lo, u64& hi) {
    const u64 n1 = 0xBF800000BF800000ULL;
    const u64 hf = 0x3F0000003F000000ULL;
    const u64 nh = 0xBF000000BF000000ULL;
    u64 s, d, k, h;
    asm("add.rn.f32x2 %0, %1, %2;" : "=l"(s) : "l"(a), "l"(b));
    asm("fma.rn.f32x2 %0, %1, %2, %3;" : "=l"(d) : "l"(b), "l"(n1), "l"(a)); // a-b
    k = d & 0x7FFFFFFF7FFFFFFFULL;                                           // |a-b|
    asm("mul.rn.f32x2 %0, %1, %2;" : "=l"(h) : "l"(s), "l"(hf));             // 0.5(a+b)
    asm("fma.rn.f32x2 %0, %1, %2, %3;" : "=l"(lo) : "l"(k), "l"(nh), "l"(h));
    asm("fma.rn.f32x2 %0, %1, %2, %3;" : "=l"(hi) : "l"(k), "l"(hf), "l"(h));
}

__device__ __forceinline__ float med3(float a, float b, float c) {
    return fmaxf(fminf(a, b), fminf(fmaxf(a, b), c));
}

struct Row3 { u64 a, b, c; };   // packed columns (1,2) (3,4) (0,5)

__device__ __forceinline__ void emit_row(const Row3& pl, const Row3& ph,
                                         const Row3& t,
                                         float* __restrict__ dst) {
    float4 res;
    u64 loa, mia, hia, loc, mic, hic, tm;
    cex2(pl.a, t.a, loa, tm);
    cex2(ph.a, tm, mia, hia);
    cex2(pl.c, t.c, loc, tm);
    cex2(ph.c, tm, mic, hic);

    float2 la = upk(loa), lc = upk(loc);
    float2 ma = upk(mia), mc = upk(mic);
    float2 ha = upk(hia), hc = upk(hic);

    float sA  = fmaxf(la.x, la.y);
    float tA  = fminf(ha.x, ha.y);
    float q0A = fminf(ma.x, ma.y), q1A = fmaxf(ma.x, ma.y);

    u64 lob, mib, hib;
    cex2(pl.b, t.b, lob, tm);
    cex2(ph.b, tm, mib, hib);
    float2 lb = upk(lob), mb = upk(mib), hb = upk(hib);

    res.x = med3(fmaxf(lc.x, sA),
                 fmaxf(q0A, fminf(q1A, mc.x)),
                 fminf(hc.x, tA));
    res.y = med3(fmaxf(sA, lb.x),
                 fmaxf(q0A, fminf(q1A, mb.x)),
                 fminf(tA, hb.x));

    float sB  = fmaxf(lb.x, lb.y);
    float tB  = fminf(hb.x, hb.y);
    float q0B = fminf(mb.x, mb.y), q1B = fmaxf(mb.x, mb.y);

    res.z = med3(fmaxf(la.y, sB),
                 fmaxf(q0B, fminf(q1B, ma.y)),
                 fminf(ha.y, tB));
    res.w = med3(fmaxf(sB, lc.y),
                 fmaxf(q0B, fminf(q1B, mc.y)),
                 fminf(tB, hc.y));

    *reinterpret_cast<float4*>(dst) = res;
}

__global__ __launch_bounds__(128, 9)
void median3x3_kernel(const float* __restrict__ x, float* __restrict__ out) {
    const int tid   = threadIdx.x;        // 0..127
    const int lane  = tid & 31;
    const int h0    = blockIdx.x << 1;    // 2 output rows per tile
    const u32 plane = blockIdx.y;         // 0..23  (pairs with plane+24)
    const int w0    = tid << 2;

    const u32 base = plane * (u32)(H * W);

    // frame rows f0..f3 = input rows h0-1 .. h0+2 (reflected at edges)
    const u32 o1 = base + (u32)h0 * W;
    const u32 o2 = o1 + W;
    const u32 o0 = (h0 == 0)     ? o2 : o1 - W;   // reflect row -1 -> 1
    const u32 o3 = (h0 + 2 >= H) ? o1 : o2 + W;   // reflect row H -> H-2

    // ---- ALL 8 vector loads issued back-to-back (MLP 8) ----
    float4 a0 = *reinterpret_cast<const float4*>(x + o0 + w0);
    float4 a1 = *reinterpret_cast<const float4*>(x + o1 + w0);
    float4 a2 = *reinterpret_cast<const float4*>(x + o2 + w0);
    float4 a3 = *reinterpret_cast<const float4*>(x + o3 + w0);
    float4 b0 = *reinterpret_cast<const float4*>(x + o0 + PLANE2 + w0);
    float4 b1 = *reinterpret_cast<const float4*>(x + o1 + PLANE2 + w0);
    float4 b2 = *reinterpret_cast<const float4*>(x + o2 + PLANE2 + w0);
    float4 b3 = *reinterpret_cast<const float4*>(x + o3 + PLANE2 + w0);

    // merged boundary fixup loads for both tiles (lanes 0 and 31 only)
    float fa0, fa1, fa2, fa3, fb0, fb1, fb2, fb3;
    if ((lane == 0) | (lane == 31)) {
        const u32 col = (lane == 0)
            ? ((w0 == 0) ? 1u : (u32)(w0 - 1))
            : ((w0 + 4 == W) ? (u32)(W - 2) : (u32)(w0 + 4));
        fa0 = x[o0 + col];
        fa1 = x[o1 + col];
        fa2 = x[o2 + col];
        fa3 = x[o3 + col];
        fb0 = x[o0 + PLANE2 + col];
        fb1 = x[o1 + PLANE2 + col];
        fb2 = x[o2 + PLANE2 + col];
        fb3 = x[o3 + PLANE2 + col];
    }

    // full tile pipeline: shuffle halos, pack, pair-sort, emit 2 rows
    auto run_tile = [&](const float4& q0, const float4& q1,
                        const float4& q2, const float4& q3,
                        float g0, float g1, float g2, float g3,
                        float* __restrict__ od) {
        float l0 = __shfl_up_sync(0xffffffffu, q0.w, 1);
        float l1 = __shfl_up_sync(0xffffffffu, q1.w, 1);
        float l2 = __shfl_up_sync(0xffffffffu, q2.w, 1);
        float l3 = __shfl_up_sync(0xffffffffu, q3.w, 1);
        float e0 = __shfl_down_sync(0xffffffffu, q0.x, 1);
        float e1 = __shfl_down_sync(0xffffffffu, q1.x, 1);
        float e2 = __shfl_down_sync(0xffffffffu, q2.x, 1);
        float e3 = __shfl_down_sync(0xffffffffu, q3.x, 1);
        if (lane == 0)  { l0 = g0; l1 = g1; l2 = g2; l3 = g3; }
        if (lane == 31) { e0 = g0; e1 = g1; e2 = g2; e3 = g3; }

        Row3 f0, f1, f2, f3;
        f0.a = pk(q0.x, q0.y); f0.b = pk(q0.z, q0.w); f0.c = pk(l0, e0);
        f1.a = pk(q1.x, q1.y); f1.b = pk(q1.z, q1.w); f1.c = pk(l1, e1);
        f2.a = pk(q2.x, q2.y); f2.b = pk(q2.z, q2.w); f2.c = pk(l2, e2);
        f3.a = pk(q3.x, q3.y); f3.b = pk(q3.z, q3.w); f3.c = pk(l3, e3);

        Row3 pl, ph;                      // pair sort rows f1,f2
        cex2(f1.a, f2.a, pl.a, ph.a);
        cex2(f1.b, f2.b, pl.b, ph.b);
        cex2(f1.c, f2.c, pl.c, ph.c);

        emit_row(pl, ph, f0, od);         // output row h0
        emit_row(pl, ph, f3, od + W);     // output row h0+1
    };

    float* od = out + o1 + w0;
    run_tile(a0, a1, a2, a3, fa0, fa1, fa2, fa3, od);           // plane p
    run_tile(b0, b1, b2, b3, fb0, fb1, fb2, fb3, od + PLANE2);  // plane p+24
}

extern "C" void kernel_launch(void* const* d_in, const int* in_sizes, int n_in,
                              void* d_out, int out_size) {
    const float* x = (const float*)d_in[0];
    float* out = (float*)d_out;
    dim3 grid(H / 2, 24);    // 256 row-pairs x 24 plane-pairs = 6144 blocks
    dim3 block(128);
    median3x3_kernel<<<grid, block>>>(x, out);
}